// round 16
// baseline (speedup 1.0000x reference)
#include <cuda_runtime.h>
#include <cuda_bf16.h>

#define NN 1024
#define MM 256
#define BB 512
#define LL 10
#define BETA 0.01f

#define SK 16                 // orig k per stage
#define TAB_OFF 0             // 1055 entries x 32B = 33760 (pad 33792)
#define W2A_OFF 33792         // 32 rows x 544B = 17408
#define B_OFF   51200         // 3-deep ring x 16384 (128 slot-rows x 128B)
#define B_STAGE 16384
#define SMEM_TOTAL 100352     // x2 CTAs = 200704 <= 227KB

typedef unsigned u32;
typedef unsigned short u16;

// ONLY global scratch: x planes [rh, rl, ih, il], ping-pong. 8MB total (proven budget).
__device__ __nv_bfloat16 gBx[2][(size_t)4 * NN * BB];

// ---------------- helpers ----------------
__device__ __forceinline__ u32 s2u(const void* p) {
    u32 a;
    asm("{ .reg .u64 t; cvta.to.shared.u64 t, %1; cvt.u32.u64 %0, t; }" : "=r"(a) : "l"(p));
    return a;
}
#define SWZ(o) ((o) ^ (((o) >> 3) & 0x70))

__device__ __forceinline__ void cpa16(u32 dst, const void* src) {
    asm volatile("cp.async.cg.shared.global [%0], [%1], 16;" :: "r"(dst), "l"(src));
}
__device__ __forceinline__ void cp_commit() {
    asm volatile("cp.async.commit_group;" ::: "memory");
}
template <int N_> __device__ __forceinline__ void cp_wait() {
    asm volatile("cp.async.wait_group %0;" :: "n"(N_) : "memory");
}
__device__ __forceinline__ void sts128(u32 a, u32 x, u32 y, u32 z, u32 w) {
    asm volatile("st.shared.v4.b32 [%0], {%1,%2,%3,%4};"
                 :: "r"(a), "r"(x), "r"(y), "r"(z), "r"(w) : "memory");
}
__device__ __forceinline__ void ldsm4(u32& r0, u32& r1, u32& r2, u32& r3, u32 a) {
    asm volatile("ldmatrix.sync.aligned.m8n8.x4.shared.b16 {%0,%1,%2,%3}, [%4];"
                 : "=r"(r0), "=r"(r1), "=r"(r2), "=r"(r3) : "r"(a));
}
__device__ __forceinline__ void ldsm4t(u32& r0, u32& r1, u32& r2, u32& r3, u32 a) {
    asm volatile("ldmatrix.sync.aligned.m8n8.x4.trans.shared.b16 {%0,%1,%2,%3}, [%4];"
                 : "=r"(r0), "=r"(r1), "=r"(r2), "=r"(r3) : "r"(a));
}
__device__ __forceinline__ void hmma(float& d0, float& d1, float& d2, float& d3,
                                     u32 a0, u32 a1, u32 a2, u32 a3, u32 b0, u32 b1) {
    asm volatile("mma.sync.aligned.m16n8k16.row.col.f32.bf16.bf16.f32 "
                 "{%0,%1,%2,%3}, {%4,%5,%6,%7}, {%8,%9}, {%0,%1,%2,%3};"
                 : "+f"(d0), "+f"(d1), "+f"(d2), "+f"(d3)
                 : "r"(a0), "r"(a1), "r"(a2), "r"(a3), "r"(b0), "r"(b1));
}
__device__ __forceinline__ void split2u(float v, u16& h, u16& lo) {
    __nv_bfloat16 hb = __float2bfloat16(v);
    h = __bfloat16_as_ushort(hb);
    lo = __bfloat16_as_ushort(__float2bfloat16(v - __bfloat162float(hb)));
}
__device__ __forceinline__ u32 pk(u16 lo, u16 hi) { return (u32)lo | ((u32)hi << 16); }

// ---------------- pre-kernel: y planes [rh, rl, ih, il] into d_out scratch ----------------
__global__ void makeBy(const float* __restrict__ y_re, const float* __restrict__ y_im,
                       float* __restrict__ dout)
{
    int e = blockIdx.x * 256 + threadIdx.x;    // over MM*BB
    int n = e & 511;
    int m = e >> 9;
    u16 rh, rl, ih, il;
    split2u(y_re[(size_t)m * BB + n], rh, rl);
    split2u(y_im[(size_t)m * BB + n], ih, il);
    __nv_bfloat16* yp = (__nv_bfloat16*)dout;
    size_t o = (size_t)m * BB + n;
    yp[o]                       = __ushort_as_bfloat16(rh);
    yp[o + (size_t)MM * BB]     = __ushort_as_bfloat16(rl);
    yp[o + (size_t)2 * MM * BB] = __ushort_as_bfloat16(ih);
    yp[o + (size_t)3 * MM * BB] = __ushort_as_bfloat16(il);
}

// ---------------- B stage: 16 k x 8 slot-rows x 128B via cp.async (64 threads) ----------------
// slot j -> plane [xrh,xrl,xrh,xrl, xih,xil,xih,xil] = (j&1) + ((j>>2)<<1)
__device__ __forceinline__ void load_b(u32 bstage, int k0, int tid, int nBase,
                                       const __nv_bfloat16* __restrict__ Bx,
                                       const __nv_bfloat16* __restrict__ Yp)
{
#pragma unroll
    for (int rep = 0; rep < 16; rep++) {
        int idx = tid + rep * 64;
        int row = idx >> 3, seg = idx & 7;
        int k = k0 + (row >> 3);
        int j = row & 7;
        int p = (j & 1) + ((j >> 2) << 1);
        const __nv_bfloat16* src = (k < 1024)
            ? (Bx + ((size_t)p * NN + k) * BB + nBase + seg * 8)
            : (Yp + ((size_t)p * MM + (k - 1024)) * BB + nBase + seg * 8);
        cpa16(bstage + SWZ((u32)(row * 128 + seg * 16)), src);
    }
    cp_commit();
}

// ---------------- W2 A stage (single buffer): 32 rows x 16 k, 32B entries, 544B stride ----
__device__ __forceinline__ void build_w2(u32 w2base, int k0, int tid, int l, int mOrig,
                                         const float* __restrict__ W2_re,
                                         const float* __restrict__ W2_im)
{
#pragma unroll
    for (int rep = 0; rep < 8; rep++) {
        int q = tid + rep * 64;
        int rl = q >> 4, dk = q & 15;
        int kg = k0 + dk - 1024;
        size_t g = ((size_t)l * NN + mOrig + rl) * MM + kg;
        float zr = W2_re[g], zi = W2_im[g];
        u16 rh, rl2, ih, il;
        split2u(zr, rh, rl2);
        split2u(zi, ih, il);
        u16 nh = ih ^ 0x8000, nl = il ^ 0x8000;
        u32 base = w2base + (u32)rl * 544 + (u32)dk * 32;
        sts128(base,      pk(rh, rh), pk(rl2, rl2), pk(nh, nh), pk(nl, nl));
        sts128(base + 16, pk(ih, ih), pk(il, il),   pk(rh, rh), pk(rl2, rl2));
    }
}

// ---------------- fused layer (64 threads = 2 warps, warp tile 32M' x 64N) ----------------
__global__ __launch_bounds__(64, 2)
void gemm_layer(int l, int kStart, int last,
                const float* __restrict__ v_re, const float* __restrict__ v_im,
                const float* __restrict__ W2_re, const float* __restrict__ W2_im,
                float* __restrict__ dout, int cur)
{
    extern __shared__ __align__(16) char smem[];
    const u32 sb = s2u(smem);
    const int tid = threadIdx.x, wid = tid >> 5, lane = tid & 31;
    const int wm = wid;                        // 2 warps stacked in M'
    const int mOrig = blockIdx.y * 32;         // 32 orig rows per CTA (M' = 64)
    const int nBase = blockIdx.x * 64;
    const __nv_bfloat16* Bx = gBx[cur];
    __nv_bfloat16* BxOut = gBx[cur ^ 1];
    const __nv_bfloat16* Yp = (const __nv_bfloat16*)dout;

    // Static Toeplitz table: entry tl (t = mOrig + tl), 1055 entries: [Re 16B | Im 16B]
    // Re = [rh,rh,rl,rl, nh,nh,nl,nl], Im = [ih,ih,il,il, rh,rh,rl,rl]
    if (kStart == 0) {
        for (int tl = tid; tl < 1055; tl += 64) {
            int t = mOrig + tl;
            float zr, zi;
            if (t <= 1023) { int j = 1023 - t; zr = v_re[l * NN + j]; zi = -v_im[l * NN + j]; }
            else           { int j = t - 1023; zr = v_re[l * NN + j]; zi =  v_im[l * NN + j]; }
            u16 rh, rl, ih, il;
            split2u(zr, rh, rl);
            split2u(zi, ih, il);
            u16 nh = ih ^ 0x8000, nl = il ^ 0x8000;
            sts128(sb + TAB_OFF + tl * 32,      pk(rh, rh), pk(rl, rl), pk(nh, nh), pk(nl, nl));
            sts128(sb + TAB_OFF + tl * 32 + 16, pk(ih, ih), pk(il, il), pk(rh, rh), pk(rl, rl));
        }
    }

    const int ST = (1280 - kStart) / SK;

    // Per-thread A lane bases. Frag h rows: Rl = wm*32 + h*16 + (lane&15).
    const int Rl0 = wm * 32 + (lane & 15), Rl1 = Rl0 + 16;
    const int rl0 = Rl0 >> 1, rl1 = Rl1 >> 1;
    const int ty0 = Rl0 & 1,  ty1 = Rl1 & 1;
    const u32 khalf = (u32)(lane >> 4);
    const u32 tb0 = sb + TAB_OFF + (u32)(rl0 + 1023) * 32 + (u32)ty0 * 16 - khalf * 32;
    const u32 tb1 = sb + TAB_OFF + (u32)(rl1 + 1023) * 32 + (u32)ty1 * 16 - khalf * 32;
    const u32 wb0 = sb + W2A_OFF + (u32)rl0 * 544 + (u32)ty0 * 16 + khalf * 32;
    const u32 wb1 = sb + W2A_OFF + (u32)rl1 * 544 + (u32)ty1 * 16 + khalf * 32;
    // B: warp covers all 64 N cols; 4 x 16-col groups at byte offsets 0,32,64,96
    const u32 bl = (u32)((lane & 15) * 128 + (int)khalf * 16);
    u32 sB[4];
#pragma unroll
    for (int j = 0; j < 4; j++) sB[j] = SWZ(bl + (u32)j * 32);

    float4 acc[2][8];
#pragma unroll
    for (int i = 0; i < 2; i++)
#pragma unroll
        for (int j = 0; j < 8; j++) { acc[i][j].x = 0.f; acc[i][j].y = 0.f; acc[i][j].z = 0.f; acc[i][j].w = 0.f; }

    // Prologue: 2 stages in flight (3-deep ring, wait<1>)
    load_b(sb + B_OFF + 0 * B_STAGE, kStart + 0 * SK, tid, nBase, Bx, Yp);
    load_b(sb + B_OFF + 1 * B_STAGE, kStart + 1 * SK, tid, nBase, Bx, Yp);

    u32 fA0[2][4], fA1[2][4], fB[2][4][4];    // chunk pipeline (2 sets)
    int bi = 0, li = 2;

    for (int s = 0; s < ST; s++) {
        const int k0 = kStart + s * SK;
        const bool toep = (k0 < 1024);
        cp_wait<1>();            // stage-s group complete (s+1 may be in flight)
        __syncthreads();         // B(s) visible; all warps past stage s-1
        if (s + 2 < ST) load_b(sb + B_OFF + li * B_STAGE, k0 + 2 * SK, tid, nBase, Bx, Yp);
        else            cp_commit();   // dummy: keep group arithmetic uniform
        li = (li == 2) ? 0 : li + 1;
        if (!toep) {
            build_w2(sb + W2A_OFF, k0, tid, l, mOrig, W2_re, W2_im);
            __syncthreads();     // single-buffer W2A visible
        }

        const u32 bcur = sb + B_OFF + bi * B_STAGE;
        bi = (bi == 2) ? 0 : bi + 1;
        u32 a0base, a1base; int astep;
        if (toep) { a0base = tb0 - (u32)k0 * 32; a1base = tb1 - (u32)k0 * 32; astep = -64; }
        else      { a0base = wb0;                a1base = wb1;                astep =  64; }

        // chunk pipeline: 8 chunks (chunk = 2 orig k = 16 slots), 6 ldsm + 16 hmma each
        {
            ldsm4(fA0[0][0], fA0[0][1], fA0[0][2], fA0[0][3], a0base);
            ldsm4(fA1[0][0], fA1[0][1], fA1[0][2], fA1[0][3], a1base);
#pragma unroll
            for (int j = 0; j < 4; j++)
                ldsm4t(fB[0][j][0], fB[0][j][1], fB[0][j][2], fB[0][j][3], bcur + sB[j]);
        }
#pragma unroll
        for (int c = 0; c < 8; c++) {
            const int pc = c & 1, nc = pc ^ 1;
            if (c + 1 < 8) {
                const u32 aoff = (u32)((c + 1) * astep);
                const u32 boff = (u32)((c + 1) * 2048);
                ldsm4(fA0[nc][0], fA0[nc][1], fA0[nc][2], fA0[nc][3], a0base + aoff);
                ldsm4(fA1[nc][0], fA1[nc][1], fA1[nc][2], fA1[nc][3], a1base + aoff);
#pragma unroll
                for (int j = 0; j < 4; j++)
                    ldsm4t(fB[nc][j][0], fB[nc][j][1], fB[nc][j][2], fB[nc][j][3],
                           bcur + boff + sB[j]);
            }
#pragma unroll
            for (int j = 0; j < 4; j++) {
                hmma(acc[0][2*j].x,   acc[0][2*j].y,   acc[0][2*j].z,   acc[0][2*j].w,
                     fA0[pc][0], fA0[pc][1], fA0[pc][2], fA0[pc][3], fB[pc][j][0], fB[pc][j][1]);
                hmma(acc[0][2*j+1].x, acc[0][2*j+1].y, acc[0][2*j+1].z, acc[0][2*j+1].w,
                     fA0[pc][0], fA0[pc][1], fA0[pc][2], fA0[pc][3], fB[pc][j][2], fB[pc][j][3]);
                hmma(acc[1][2*j].x,   acc[1][2*j].y,   acc[1][2*j].z,   acc[1][2*j].w,
                     fA1[pc][0], fA1[pc][1], fA1[pc][2], fA1[pc][3], fB[pc][j][0], fB[pc][j][1]);
                hmma(acc[1][2*j+1].x, acc[1][2*j+1].y, acc[1][2*j+1].z, acc[1][2*j+1].w,
                     fA1[pc][0], fA1[pc][1], fA1[pc][2], fA1[pc][3], fB[pc][j][2], fB[pc][j][3]);
            }
        }
    }
    __syncthreads();   // all warps done before sC overwrites the table region

    // ---- epilogue: C -> SMEM (table region dead), threshold, emit planes ----
    float* sC = (float*)smem;   // [64][66] = 16896B <= 33792
#pragma unroll
    for (int im = 0; im < 2; im++)
#pragma unroll
        for (int jn = 0; jn < 8; jn++) {
            int r0 = wm * 32 + im * 16 + (lane >> 2);
            int c0 = jn * 8 + (lane & 3) * 2;
            sC[r0 * 66 + c0]           = acc[im][jn].x;
            sC[r0 * 66 + c0 + 1]       = acc[im][jn].y;
            sC[(r0 + 8) * 66 + c0]     = acc[im][jn].z;
            sC[(r0 + 8) * 66 + c0 + 1] = acc[im][jn].w;
        }
    __syncthreads();

    const int cl = tid;                // 64 threads = 64 cols
    for (int t = 0; t < 32; t++) {
        float zr = sC[(2 * t) * 66 + cl];
        float zi = sC[(2 * t + 1) * 66 + cl];
        float mag = sqrtf(zr * zr + zi * zi);
        float sf = fmaxf(mag - BETA, 0.f) / fmaxf(mag, 1e-30f);
        float xr = zr * sf, xi = zi * sf;
        int R  = mOrig + t;
        int gc = nBase + cl;
        if (last) {
            ((float*)BxOut)[(size_t)R * BB + gc] = xr;   // fp32 Re(x); finalize copies out
        } else {
            u16 rh, rl, ih, il;
            split2u(xr, rh, rl);
            split2u(xi, ih, il);
            size_t o = (size_t)R * BB + gc;
            BxOut[o]                       = __ushort_as_bfloat16(rh);
            BxOut[o + (size_t)NN * BB]     = __ushort_as_bfloat16(rl);
            BxOut[o + (size_t)2 * NN * BB] = __ushort_as_bfloat16(ih);
            BxOut[o + (size_t)3 * NN * BB] = __ushort_as_bfloat16(il);
        }
    }
}

// ---------------- finalize: copy fp32 Re(x) from gBx[0] into d_out ----------------
__global__ void finalize(float* __restrict__ dst)
{
    const float* src = (const float*)gBx[0];     // layer 9 (cur=1) wrote gBx[0]
    long i = (long)blockIdx.x * 256 + threadIdx.x;
    if (i < (long)NN * BB) dst[i] = src[i];
}

extern "C" void kernel_launch(void* const* d_in, const int* in_sizes, int n_in,
                              void* d_out, int out_size)
{
    // Bind inputs by element count; first in size class = real part (confirmed R5).
    const float *v_re = 0, *v_im = 0, *W2_re = 0, *W2_im = 0, *y_re = 0, *y_im = 0;
    const long SV = (long)LL * NN, SW_ = (long)LL * NN * MM, SY = (long)MM * BB;
    for (int i = 0; i < n_in; i++) {
        const float* p = (const float*)d_in[i];
        long sz = in_sizes[i];
        if (sz == SV || sz == 4 * SV)        { if (!v_re)  v_re  = p; else v_im  = p; }
        else if (sz == SW_ || sz == 4 * SW_) { if (!W2_re) W2_re = p; else W2_im = p; }
        else if (sz == SY || sz == 4 * SY)   { if (!y_re)  y_re  = p; else y_im  = p; }
    }
    if (!v_re || !v_im || !W2_re || !W2_im || !y_re || !y_im) return;

    cudaFuncSetAttribute(gemm_layer, cudaFuncAttributeMaxDynamicSharedMemorySize, SMEM_TOTAL);

    makeBy<<<(MM * BB) / 256, 256>>>(y_re, y_im, (float*)d_out);

    dim3 grid(BB / 64, NN / 32);   // (8, 32) = 256 CTAs
    for (int l = 0; l < LL; l++) {
        int kStart = (l == 0) ? 1024 : 0;
        gemm_layer<<<grid, 64, SMEM_TOTAL>>>(l, kStart, l == LL - 1,
                                             v_re, v_im, W2_re, W2_im,
                                             (float*)d_out, l & 1);
    }
    finalize<<<(NN * BB) / 256, 256>>>((float*)d_out);
}

// round 17
// speedup vs baseline: 1.1764x; 1.1764x over previous
#include <cuda_runtime.h>
#include <cuda_bf16.h>

#define NN 1024
#define MM 256
#define BB 512
#define LL 10
#define BETA 0.01f

#define SK 16                 // orig k per stage
#define TAB_OFF 0             // 1055 entries x 32B = 33760 (pad 33792)
#define W2A_OFF 33792         // 32 rows x 544B = 17408
#define B_OFF   51200         // 3-deep ring x 16384 (128 slot-rows x 128B)
#define B_STAGE 16384
#define SMEM_TOTAL 100352     // x2 CTAs = 200704 <= 227KB

typedef unsigned u32;
typedef unsigned short u16;

// ONLY global scratch: x planes [rh, rl, ih, il], ping-pong. 8MB total (proven budget).
__device__ __nv_bfloat16 gBx[2][(size_t)4 * NN * BB];

// ---------------- helpers ----------------
__device__ __forceinline__ u32 s2u(const void* p) {
    u32 a;
    asm("{ .reg .u64 t; cvta.to.shared.u64 t, %1; cvt.u32.u64 %0, t; }" : "=r"(a) : "l"(p));
    return a;
}
#define SWZ(o) ((o) ^ (((o) >> 3) & 0x70))

__device__ __forceinline__ void cpa16(u32 dst, const void* src) {
    asm volatile("cp.async.cg.shared.global [%0], [%1], 16;" :: "r"(dst), "l"(src));
}
__device__ __forceinline__ void cp_commit() {
    asm volatile("cp.async.commit_group;" ::: "memory");
}
template <int N_> __device__ __forceinline__ void cp_wait() {
    asm volatile("cp.async.wait_group %0;" :: "n"(N_) : "memory");
}
__device__ __forceinline__ void sts128(u32 a, u32 x, u32 y, u32 z, u32 w) {
    asm volatile("st.shared.v4.b32 [%0], {%1,%2,%3,%4};"
                 :: "r"(a), "r"(x), "r"(y), "r"(z), "r"(w) : "memory");
}
__device__ __forceinline__ void ldsm4(u32& r0, u32& r1, u32& r2, u32& r3, u32 a) {
    asm volatile("ldmatrix.sync.aligned.m8n8.x4.shared.b16 {%0,%1,%2,%3}, [%4];"
                 : "=r"(r0), "=r"(r1), "=r"(r2), "=r"(r3) : "r"(a));
}
__device__ __forceinline__ void ldsm4t(u32& r0, u32& r1, u32& r2, u32& r3, u32 a) {
    asm volatile("ldmatrix.sync.aligned.m8n8.x4.trans.shared.b16 {%0,%1,%2,%3}, [%4];"
                 : "=r"(r0), "=r"(r1), "=r"(r2), "=r"(r3) : "r"(a));
}
__device__ __forceinline__ void hmma(float& d0, float& d1, float& d2, float& d3,
                                     u32 a0, u32 a1, u32 a2, u32 a3, u32 b0, u32 b1) {
    asm volatile("mma.sync.aligned.m16n8k16.row.col.f32.bf16.bf16.f32 "
                 "{%0,%1,%2,%3}, {%4,%5,%6,%7}, {%8,%9}, {%0,%1,%2,%3};"
                 : "+f"(d0), "+f"(d1), "+f"(d2), "+f"(d3)
                 : "r"(a0), "r"(a1), "r"(a2), "r"(a3), "r"(b0), "r"(b1));
}
__device__ __forceinline__ void split2u(float v, u16& h, u16& lo) {
    __nv_bfloat16 hb = __float2bfloat16(v);
    h = __bfloat16_as_ushort(hb);
    lo = __bfloat16_as_ushort(__float2bfloat16(v - __bfloat162float(hb)));
}
__device__ __forceinline__ u32 pk(u16 lo, u16 hi) { return (u32)lo | ((u32)hi << 16); }

// ---------------- pre-kernel: y planes [rh, rl, ih, il] into d_out scratch ----------------
__global__ void makeBy(const float* __restrict__ y_re, const float* __restrict__ y_im,
                       float* __restrict__ dout)
{
    int e = blockIdx.x * 256 + threadIdx.x;    // over MM*BB
    int n = e & 511;
    int m = e >> 9;
    u16 rh, rl, ih, il;
    split2u(y_re[(size_t)m * BB + n], rh, rl);
    split2u(y_im[(size_t)m * BB + n], ih, il);
    __nv_bfloat16* yp = (__nv_bfloat16*)dout;
    size_t o = (size_t)m * BB + n;
    yp[o]                       = __ushort_as_bfloat16(rh);
    yp[o + (size_t)MM * BB]     = __ushort_as_bfloat16(rl);
    yp[o + (size_t)2 * MM * BB] = __ushort_as_bfloat16(ih);
    yp[o + (size_t)3 * MM * BB] = __ushort_as_bfloat16(il);
}

// ---------------- B stage: 16 k x 8 slot-rows x 128B via cp.async (128 threads) ----------------
// slot j -> plane [xrh,xrl,xrh,xrl, xih,xil,xih,xil] = (j&1) + ((j>>2)<<1)
__device__ __forceinline__ void load_b(u32 bstage, int k0, int tid, int nBase,
                                       const __nv_bfloat16* __restrict__ Bx,
                                       const __nv_bfloat16* __restrict__ Yp)
{
#pragma unroll
    for (int rep = 0; rep < 8; rep++) {
        int idx = tid + rep * 128;
        int row = idx >> 3, seg = idx & 7;
        int k = k0 + (row >> 3);
        int j = row & 7;
        int p = (j & 1) + ((j >> 2) << 1);
        const __nv_bfloat16* src = (k < 1024)
            ? (Bx + ((size_t)p * NN + k) * BB + nBase + seg * 8)
            : (Yp + ((size_t)p * MM + (k - 1024)) * BB + nBase + seg * 8);
        cpa16(bstage + SWZ((u32)(row * 128 + seg * 16)), src);
    }
    cp_commit();
}

// ---------------- W2 A stage (single buffer): 32 rows x 16 k, 32B entries, 544B stride ----
__device__ __forceinline__ void build_w2(u32 w2base, int k0, int tid, int l, int mOrig,
                                         const float* __restrict__ W2_re,
                                         const float* __restrict__ W2_im)
{
#pragma unroll
    for (int rep = 0; rep < 4; rep++) {
        int q = tid + rep * 128;
        int rl = q >> 4, dk = q & 15;
        int kg = k0 + dk - 1024;
        size_t g = ((size_t)l * NN + mOrig + rl) * MM + kg;
        float zr = W2_re[g], zi = W2_im[g];
        u16 rh, rl2, ih, il;
        split2u(zr, rh, rl2);
        split2u(zi, ih, il);
        u16 nh = ih ^ 0x8000, nl = il ^ 0x8000;
        u32 base = w2base + (u32)rl * 544 + (u32)dk * 32;
        sts128(base,      pk(rh, rh), pk(rl2, rl2), pk(nh, nh), pk(nl, nl));
        sts128(base + 16, pk(ih, ih), pk(il, il),   pk(rh, rh), pk(rl2, rl2));
    }
}

// ---------------- fused layer (128 thr: warps = wm{0,1} x kg{0,1}, tile 32M'x64N, split-K) ----
__global__ __launch_bounds__(128, 2)
void gemm_layer(int l, int kStart, int last,
                const float* __restrict__ v_re, const float* __restrict__ v_im,
                const float* __restrict__ W2_re, const float* __restrict__ W2_im,
                float* __restrict__ dout, int cur)
{
    extern __shared__ __align__(16) char smem[];
    const u32 sb = s2u(smem);
    const int tid = threadIdx.x, wid = tid >> 5, lane = tid & 31;
    const int wm = wid & 1;                    // M'-half
    const int kg = wid >> 1;                   // K-group (split-K)
    const int mOrig = blockIdx.y * 32;         // 32 orig rows per CTA (M' = 64)
    const int nBase = blockIdx.x * 64;
    const __nv_bfloat16* Bx = gBx[cur];
    __nv_bfloat16* BxOut = gBx[cur ^ 1];
    const __nv_bfloat16* Yp = (const __nv_bfloat16*)dout;

    // Static Toeplitz table: entry tl (t = mOrig + tl), 1055 entries: [Re 16B | Im 16B]
    // Re = [rh,rh,rl,rl, nh,nh,nl,nl], Im = [ih,ih,il,il, rh,rh,rl,rl]
    if (kStart == 0) {
        for (int tl = tid; tl < 1055; tl += 128) {
            int t = mOrig + tl;
            float zr, zi;
            if (t <= 1023) { int j = 1023 - t; zr = v_re[l * NN + j]; zi = -v_im[l * NN + j]; }
            else           { int j = t - 1023; zr = v_re[l * NN + j]; zi =  v_im[l * NN + j]; }
            u16 rh, rl, ih, il;
            split2u(zr, rh, rl);
            split2u(zi, ih, il);
            u16 nh = ih ^ 0x8000, nl = il ^ 0x8000;
            sts128(sb + TAB_OFF + tl * 32,      pk(rh, rh), pk(rl, rl), pk(nh, nh), pk(nl, nl));
            sts128(sb + TAB_OFF + tl * 32 + 16, pk(ih, ih), pk(il, il), pk(rh, rh), pk(rl, rl));
        }
    }

    const int ST = (1280 - kStart) / SK;

    // Per-thread A lane bases. Frag h rows: Rl = wm*32 + h*16 + (lane&15).
    const int Rl0 = wm * 32 + (lane & 15), Rl1 = Rl0 + 16;
    const int rl0 = Rl0 >> 1, rl1 = Rl1 >> 1;
    const int ty0 = Rl0 & 1,  ty1 = Rl1 & 1;
    const u32 khalf = (u32)(lane >> 4);
    const u32 tb0 = sb + TAB_OFF + (u32)(rl0 + 1023) * 32 + (u32)ty0 * 16 - khalf * 32;
    const u32 tb1 = sb + TAB_OFF + (u32)(rl1 + 1023) * 32 + (u32)ty1 * 16 - khalf * 32;
    const u32 wb0 = sb + W2A_OFF + (u32)rl0 * 544 + (u32)ty0 * 16 + khalf * 32;
    const u32 wb1 = sb + W2A_OFF + (u32)rl1 * 544 + (u32)ty1 * 16 + khalf * 32;
    // B: warp covers all 64 N cols; 4 x 16-col groups at byte offsets 0,32,64,96
    const u32 bl = (u32)((lane & 15) * 128 + (int)khalf * 16);
    u32 sB[4];
#pragma unroll
    for (int j = 0; j < 4; j++) sB[j] = SWZ(bl + (u32)j * 32);

    float4 acc[2][8];
#pragma unroll
    for (int i = 0; i < 2; i++)
#pragma unroll
        for (int j = 0; j < 8; j++) { acc[i][j].x = 0.f; acc[i][j].y = 0.f; acc[i][j].z = 0.f; acc[i][j].w = 0.f; }

    // Prologue: 2 stages in flight (3-deep ring, wait<1>)
    load_b(sb + B_OFF + 0 * B_STAGE, kStart + 0 * SK, tid, nBase, Bx, Yp);
    load_b(sb + B_OFF + 1 * B_STAGE, kStart + 1 * SK, tid, nBase, Bx, Yp);

    u32 fA0[2][4], fA1[2][4], fB[2][4][4];    // chunk pipeline (2 sets)
    int bi = 0, li = 2;

    for (int s = 0; s < ST; s++) {
        const int k0 = kStart + s * SK;
        const bool toep = (k0 < 1024);
        cp_wait<1>();            // stage-s group complete (s+1 may be in flight)
        __syncthreads();         // B(s) visible; all warps past stage s-1
        if (s + 2 < ST) load_b(sb + B_OFF + li * B_STAGE, k0 + 2 * SK, tid, nBase, Bx, Yp);
        else            cp_commit();   // dummy: keep group arithmetic uniform
        li = (li == 2) ? 0 : li + 1;
        if (!toep) {
            build_w2(sb + W2A_OFF, k0, tid, l, mOrig, W2_re, W2_im);
            __syncthreads();     // single-buffer W2A visible
        }

        const u32 bcur = sb + B_OFF + bi * B_STAGE;
        bi = (bi == 2) ? 0 : bi + 1;
        u32 a0base, a1base; int astep;
        if (toep) { a0base = tb0 - (u32)k0 * 32; a1base = tb1 - (u32)k0 * 32; astep = -64; }
        else      { a0base = wb0;                a1base = wb1;                astep =  64; }

        // split-K: this warp handles chunks c = 2*i + kg, i = 0..3 (chunk = 2 orig k)
        {
            const int c0i = kg;
            const u32 aoff0 = (u32)(c0i * astep);
            const u32 boff0 = (u32)(c0i * 2048);
            ldsm4(fA0[0][0], fA0[0][1], fA0[0][2], fA0[0][3], a0base + aoff0);
            ldsm4(fA1[0][0], fA1[0][1], fA1[0][2], fA1[0][3], a1base + aoff0);
#pragma unroll
            for (int j = 0; j < 4; j++)
                ldsm4t(fB[0][j][0], fB[0][j][1], fB[0][j][2], fB[0][j][3],
                       bcur + boff0 + sB[j]);
        }
#pragma unroll
        for (int i = 0; i < 4; i++) {
            const int pc = i & 1, nc = pc ^ 1;
            if (i + 1 < 4) {
                const int cn = 2 * (i + 1) + kg;
                const u32 aoff = (u32)(cn * astep);
                const u32 boff = (u32)(cn * 2048);
                ldsm4(fA0[nc][0], fA0[nc][1], fA0[nc][2], fA0[nc][3], a0base + aoff);
                ldsm4(fA1[nc][0], fA1[nc][1], fA1[nc][2], fA1[nc][3], a1base + aoff);
#pragma unroll
                for (int j = 0; j < 4; j++)
                    ldsm4t(fB[nc][j][0], fB[nc][j][1], fB[nc][j][2], fB[nc][j][3],
                           bcur + boff + sB[j]);
            }
#pragma unroll
            for (int j = 0; j < 4; j++) {
                hmma(acc[0][2*j].x,   acc[0][2*j].y,   acc[0][2*j].z,   acc[0][2*j].w,
                     fA0[pc][0], fA0[pc][1], fA0[pc][2], fA0[pc][3], fB[pc][j][0], fB[pc][j][1]);
                hmma(acc[0][2*j+1].x, acc[0][2*j+1].y, acc[0][2*j+1].z, acc[0][2*j+1].w,
                     fA0[pc][0], fA0[pc][1], fA0[pc][2], fA0[pc][3], fB[pc][j][2], fB[pc][j][3]);
                hmma(acc[1][2*j].x,   acc[1][2*j].y,   acc[1][2*j].z,   acc[1][2*j].w,
                     fA1[pc][0], fA1[pc][1], fA1[pc][2], fA1[pc][3], fB[pc][j][0], fB[pc][j][1]);
                hmma(acc[1][2*j+1].x, acc[1][2*j+1].y, acc[1][2*j+1].z, acc[1][2*j+1].w,
                     fA1[pc][0], fA1[pc][1], fA1[pc][2], fA1[pc][3], fB[pc][j][2], fB[pc][j][3]);
            }
        }
    }
    __syncthreads();   // all warps done before sC overwrites the table region

    // ---- epilogue: split-K reduction in SMEM, threshold, emit planes ----
    float* sC = (float*)smem;   // [64][66] = 16896B <= 33792
    if (kg == 0) {
#pragma unroll
        for (int im = 0; im < 2; im++)
#pragma unroll
            for (int jn = 0; jn < 8; jn++) {
                int r0 = wm * 32 + im * 16 + (lane >> 2);
                int c0 = jn * 8 + (lane & 3) * 2;
                sC[r0 * 66 + c0]           = acc[im][jn].x;
                sC[r0 * 66 + c0 + 1]       = acc[im][jn].y;
                sC[(r0 + 8) * 66 + c0]     = acc[im][jn].z;
                sC[(r0 + 8) * 66 + c0 + 1] = acc[im][jn].w;
            }
    }
    __syncthreads();
    if (kg == 1) {
#pragma unroll
        for (int im = 0; im < 2; im++)
#pragma unroll
            for (int jn = 0; jn < 8; jn++) {
                int r0 = wm * 32 + im * 16 + (lane >> 2);
                int c0 = jn * 8 + (lane & 3) * 2;
                sC[r0 * 66 + c0]           += acc[im][jn].x;
                sC[r0 * 66 + c0 + 1]       += acc[im][jn].y;
                sC[(r0 + 8) * 66 + c0]     += acc[im][jn].z;
                sC[(r0 + 8) * 66 + c0 + 1] += acc[im][jn].w;
            }
    }
    __syncthreads();

    const int cl = tid & 63;
    const int tr = tid >> 6;           // 0..1
    for (int t = tr; t < 32; t += 2) {
        float zr = sC[(2 * t) * 66 + cl];
        float zi = sC[(2 * t + 1) * 66 + cl];
        float mag = sqrtf(zr * zr + zi * zi);
        float sf = fmaxf(mag - BETA, 0.f) / fmaxf(mag, 1e-30f);
        float xr = zr * sf, xi = zi * sf;
        int R  = mOrig + t;
        int gc = nBase + cl;
        if (last) {
            ((float*)BxOut)[(size_t)R * BB + gc] = xr;   // fp32 Re(x); finalize copies out
        } else {
            u16 rh, rl, ih, il;
            split2u(xr, rh, rl);
            split2u(xi, ih, il);
            size_t o = (size_t)R * BB + gc;
            BxOut[o]                       = __ushort_as_bfloat16(rh);
            BxOut[o + (size_t)NN * BB]     = __ushort_as_bfloat16(rl);
            BxOut[o + (size_t)2 * NN * BB] = __ushort_as_bfloat16(ih);
            BxOut[o + (size_t)3 * NN * BB] = __ushort_as_bfloat16(il);
        }
    }
}

// ---------------- finalize: copy fp32 Re(x) from gBx[0] into d_out ----------------
__global__ void finalize(float* __restrict__ dst)
{
    const float* src = (const float*)gBx[0];     // layer 9 (cur=1) wrote gBx[0]
    long i = (long)blockIdx.x * 256 + threadIdx.x;
    if (i < (long)NN * BB) dst[i] = src[i];
}

extern "C" void kernel_launch(void* const* d_in, const int* in_sizes, int n_in,
                              void* d_out, int out_size)
{
    // Bind inputs by element count; first in size class = real part (confirmed R5).
    const float *v_re = 0, *v_im = 0, *W2_re = 0, *W2_im = 0, *y_re = 0, *y_im = 0;
    const long SV = (long)LL * NN, SW_ = (long)LL * NN * MM, SY = (long)MM * BB;
    for (int i = 0; i < n_in; i++) {
        const float* p = (const float*)d_in[i];
        long sz = in_sizes[i];
        if (sz == SV || sz == 4 * SV)        { if (!v_re)  v_re  = p; else v_im  = p; }
        else if (sz == SW_ || sz == 4 * SW_) { if (!W2_re) W2_re = p; else W2_im = p; }
        else if (sz == SY || sz == 4 * SY)   { if (!y_re)  y_re  = p; else y_im  = p; }
    }
    if (!v_re || !v_im || !W2_re || !W2_im || !y_re || !y_im) return;

    cudaFuncSetAttribute(gemm_layer, cudaFuncAttributeMaxDynamicSharedMemorySize, SMEM_TOTAL);

    makeBy<<<(MM * BB) / 256, 256>>>(y_re, y_im, (float*)d_out);

    dim3 grid(BB / 64, NN / 32);   // (8, 32) = 256 CTAs
    for (int l = 0; l < LL; l++) {
        int kStart = (l == 0) ? 1024 : 0;
        gemm_layer<<<grid, 128, SMEM_TOTAL>>>(l, kStart, l == LL - 1,
                                              v_re, v_im, W2_re, W2_im,
                                              (float*)d_out, l & 1);
    }
    finalize<<<(NN * BB) / 256, 256>>>((float*)d_out);
}